// round 5
// baseline (speedup 1.0000x reference)
#include <cuda_runtime.h>

#define NS      32768
#define NT      512
#define SEASK   24
#define LEVW    512
#define SEAW    536
#define LOGW    511

#define BLOCK   32
#define NPER    21          // steady periods of 24 steps, starting at t=8
#define RSTRIDE 28          // smem row stride (floats); 28 = -4 mod 32 -> conflict-free .128
#define Y0S     12

__device__ __forceinline__ unsigned smem_u32(const void* p) {
    return (unsigned)__cvta_generic_to_shared(p);
}
__device__ __forceinline__ void cp16(unsigned dst, const void* src) {
    asm volatile("cp.async.cg.shared.global [%0], [%1], 16;\n" :: "r"(dst), "l"(src) : "memory");
}
__device__ __forceinline__ void cp_commit() {
    asm volatile("cp.async.commit_group;\n" ::: "memory");
}
template<int N> __device__ __forceinline__ void cp_wait() {
    asm volatile("cp.async.wait_group %0;\n" :: "n"(N) : "memory");
}

__global__ __launch_bounds__(BLOCK) void es_fwd_kernel(
    const float* __restrict__ y,
    const int*   __restrict__ idxs,
    const float* __restrict__ lev_sms_p,
    const float* __restrict__ init_seas_p,
    float* __restrict__ out)
{
    __shared__ __align__(16) float ybuf[3][BLOCK * RSTRIDE];  // y staging, depth-2 prefetch
    __shared__ __align__(16) float y0buf[BLOCK * Y0S];
    __shared__ __align__(16) float ltile[BLOCK * RSTRIDE];
    __shared__ __align__(16) float stile[BLOCK * RSTRIDE];
    __shared__ __align__(16) float dtile[BLOCK * RSTRIDE];

    const int tid = threadIdx.x;
    const int s0  = blockIdx.x * BLOCK;
    const int s   = s0 + tid;

    float* gl = out;
    float* gs = out + (size_t)NS * LEVW;
    float* gd = gs  + (size_t)NS * SEAW;

    const int idx = idxs[s];
    // reference derives BOTH smoothing params from lev_sms (its own quirk)
    const float a   = 1.0f / (1.0f + __expf(-lev_sms_p[idx]));
    const float oma = 1.0f - a;

    // ---- launch async y loads first (fly under init work) ----
    const char* ybase = (const char*)(y + (size_t)s0 * NT);
    const unsigned ysb[3] = { smem_u32(ybuf[0]), smem_u32(ybuf[1]), smem_u32(ybuf[2]) };

    // G0: chunk 0 -> y[:, 0:8)
    #pragma unroll
    for (int j = 0; j < 2; j++) {
        const int f = tid + 32 * j;
        const int row = f >> 1, col = f & 1;
        cp16(smem_u32(y0buf) + row * (Y0S * 4) + col * 16,
             ybase + row * (NT * 4) + col * 16);
    }
    cp_commit();
    // G1, G2: periods 0 and 1
    #pragma unroll
    for (int p = 0; p < 2; p++) {
        #pragma unroll
        for (int j = 0; j < 6; j++) {
            const int f = tid + 32 * j;
            const int row = f / 6, col = f % 6;
            cp16(ysb[p] + row * (RSTRIDE * 4) + col * 16,
                 ybase + 32 + 96 * p + row * (NT * 4) + col * 16);
        }
        cp_commit();
    }

    // ---- seasonal state in registers; emit seas cols 0..23 (streaming) ----
    float sbuf[SEASK];
    {
        const float4* isr = (const float4*)(init_seas_p + (size_t)idx * SEASK);
        float4* gsr = (float4*)(gs + (size_t)s * SEAW);
        #pragma unroll
        for (int qd = 0; qd < 6; qd++) {
            float4 v = isr[qd];
            v.x = __expf(v.x); v.y = __expf(v.y); v.z = __expf(v.z); v.w = __expf(v.w);
            sbuf[4*qd+0] = v.x; sbuf[4*qd+1] = v.y;
            sbuf[4*qd+2] = v.z; sbuf[4*qd+3] = v.w;
            __stcs(gsr + qd, v);
        }
    }

    float lev, llev;

    // ================= peel: steps 0..7 =================
    cp_wait<2>();      // G0 complete
    __syncwarp();
    {
        const float4 v0 = *(const float4*)(y0buf + tid * Y0S);
        const float4 v1 = *(const float4*)(y0buf + tid * Y0S + 4);
        float yt[8] = {v0.x, v0.y, v0.z, v0.w, v1.x, v1.y, v1.z, v1.w};
        float q_[8], nl_[8], dt_[8];

        const float st0 = sbuf[0];
        lev  = __fdividef(yt[0], st0);
        llev = __logf(lev);
        nl_[0] = lev; dt_[0] = 0.0f;

        #pragma unroll
        for (int k = 1; k < 8; k++) {
            const float sv = sbuf[k];
            q_[k]   = a * __fdividef(yt[k], sv);
            sbuf[k] = oma * sv;                      // os folded in place
        }
        #pragma unroll
        for (int k = 1; k < 8; k++) { nl_[k] = fmaf(oma, lev, q_[k]); lev = nl_[k]; }
        #pragma unroll
        for (int k = 1; k < 8; k++)
            sbuf[k] = fmaf(a, __fdividef(yt[k], nl_[k]), sbuf[k]);
        #pragma unroll
        for (int k = 1; k < 8; k++) {
            const float ll = __logf(nl_[k]);
            dt_[k] = ll - llev; llev = ll;
        }

        float* lt = ltile + tid * RSTRIDE;
        float* st = stile + tid * RSTRIDE;
        float* dt = dtile + tid * RSTRIDE;
        *(float4*)(lt)     = make_float4(nl_[0], nl_[1], nl_[2], nl_[3]);
        *(float4*)(lt + 4) = make_float4(nl_[4], nl_[5], nl_[6], nl_[7]);
        *(float4*)(st)     = make_float4(st0, sbuf[1], sbuf[2], sbuf[3]);  // col 24 = init_seas[:,0]
        *(float4*)(st + 4) = make_float4(sbuf[4], sbuf[5], sbuf[6], sbuf[7]);
        *(float4*)(dt)     = make_float4(dt_[0], dt_[1], dt_[2], dt_[3]);
        *(float4*)(dt + 4) = make_float4(dt_[4], dt_[5], dt_[6], dt_[7]);
        __syncwarp();

        #pragma unroll
        for (int j = 0; j < 2; j++) {
            const int f = tid + 32 * j;
            const int row = f >> 1, qd = f & 1;
            __stcs((float4*)(gl + (size_t)(s0 + row) * LEVW) + qd,
                   ((const float4*)(ltile + row * RSTRIDE))[qd]);
            __stcs((float4*)(gs + (size_t)(s0 + row) * SEAW + SEASK) + qd,
                   ((const float4*)(stile + row * RSTRIDE))[qd]);
        }
        #pragma unroll
        for (int j = 0; j < 7; j++) {
            const int i = tid + 32 * j;
            const int row = i / 7, k = i % 7;
            __stcs(gd + (size_t)(s0 + row) * LOGW + k, dtile[row * RSTRIDE + 1 + k]);
        }
        __syncwarp();
    }

    // ================= 21 steady periods of 24 steps =================
    #pragma unroll 1
    for (int p = 0; p < NPER; p++) {
        if (p + 2 < NPER) {
            const char* yb = ybase + 32 + (size_t)(p + 2) * 96;
            const unsigned d = ysb[(p + 2) % 3];
            #pragma unroll
            for (int j = 0; j < 6; j++) {
                const int f = tid + 32 * j;
                const int row = f / 6, col = f % 6;
                cp16(d + row * (RSTRIDE * 4) + col * 16, yb + row * (NT * 4) + col * 16);
            }
            cp_commit();
            cp_wait<2>();          // current period's group complete
        } else {
            cp_wait<0>();
        }
        __syncwarp();

        const float* ysm = ybuf[p % 3] + tid * RSTRIDE;
        float yt[SEASK], q_[SEASK], nl_[SEASK];

        #pragma unroll
        for (int m = 0; m < 6; m++) {
            const float4 v = *(const float4*)(ysm + 4 * m);
            yt[4*m+0] = v.x; yt[4*m+1] = v.y; yt[4*m+2] = v.z; yt[4*m+3] = v.w;
        }

        // batch 1: 24 independent divides; fold (1-a)*seas into sbuf in place.
        // pos = (8+k) % 24 covers each slot exactly once (read before write).
        #pragma unroll
        for (int k = 0; k < SEASK; k++) {
            const int pp = (8 + k) % SEASK;
            const float sv = sbuf[pp];
            q_[k]    = a * __fdividef(yt[k], sv);
            sbuf[pp] = oma * sv;
        }
        // the only true carried chain: 24 FFMA
        #pragma unroll
        for (int k = 0; k < SEASK; k++) { nl_[k] = fmaf(oma, lev, q_[k]); lev = nl_[k]; }
        // batch 2: 24 independent divides -> season update in place
        #pragma unroll
        for (int k = 0; k < SEASK; k++) {
            const int pp = (8 + k) % SEASK;
            sbuf[pp] = fmaf(a, __fdividef(yt[k], nl_[k]), sbuf[pp]);
        }

        // stage levels + seasons (vector STS)
        float* lt = ltile + tid * RSTRIDE;
        float* st = stile + tid * RSTRIDE;
        float* dt = dtile + tid * RSTRIDE;
        #pragma unroll
        for (int m = 0; m < 6; m++) {
            *(float4*)(lt + 4*m) = make_float4(nl_[4*m], nl_[4*m+1], nl_[4*m+2], nl_[4*m+3]);
            *(float4*)(st + 4*m) = make_float4(sbuf[(8+4*m)   % SEASK], sbuf[(9+4*m)  % SEASK],
                                               sbuf[(10+4*m)  % SEASK], sbuf[(11+4*m) % SEASK]);
        }
        // logs (24 independent LG2) + diffs, flushed as float4
        #pragma unroll
        for (int m = 0; m < 6; m++) {
            float d0, d1, d2, d3, ll;
            ll = __logf(nl_[4*m+0]); d0 = ll - llev; llev = ll;
            ll = __logf(nl_[4*m+1]); d1 = ll - llev; llev = ll;
            ll = __logf(nl_[4*m+2]); d2 = ll - llev; llev = ll;
            ll = __logf(nl_[4*m+3]); d3 = ll - llev; llev = ll;
            *(float4*)(dt + 4*m) = make_float4(d0, d1, d2, d3);
        }
        __syncwarp();

        // coalesced writeback (streaming stores; outputs never re-read)
        const int tp = 8 + 24 * p;
        #pragma unroll
        for (int j = 0; j < 6; j++) {
            const int f = tid + 32 * j;
            const int row = f / 6, c4 = f % 6;
            const int grow = s0 + row;
            __stcs((float4*)(gl + (size_t)grow * LEVW + tp + 4 * c4),
                   *(const float4*)(ltile + row * RSTRIDE + 4 * c4));
            __stcs((float4*)(gs + (size_t)grow * SEAW + tp + SEASK + 4 * c4),
                   *(const float4*)(stile + row * RSTRIDE + 4 * c4));
        }
        #pragma unroll
        for (int j = 0; j < 24; j++) {
            const int i = tid + 32 * j;
            const int row = i / 24, k = i % 24;
            __stcs(gd + (size_t)(s0 + row) * LOGW + tp - 1 + k, dtile[row * RSTRIDE + k]);
        }
        __syncwarp();
    }
}

extern "C" void kernel_launch(void* const* d_in, const int* in_sizes, int n_in,
                              void* d_out, int out_size)
{
    const float* y         = (const float*)d_in[0];
    const int*   idxs      = (const int*)  d_in[1];
    const float* lev_sms   = (const float*)d_in[2];
    const float* init_seas = (const float*)d_in[4];  // d_in[3] unused (reference quirk)
    float* out = (float*)d_out;

    es_fwd_kernel<<<NS / BLOCK, BLOCK>>>(y, idxs, lev_sms, init_seas, out);
}

// round 6
// speedup vs baseline: 1.0305x; 1.0305x over previous
#include <cuda_runtime.h>
#include <cuda.h>

#define NS      32768
#define NT      512
#define SEASK   24
#define LEVW    512
#define SEAW    536
#define LOGW    511

#define BLOCK   32
#define NPER    21          // steady periods of 24 steps, starting at t=8
#define RSTRIDE 28          // y/d smem row stride (floats): conflict-free .128
#define LPACK   24          // packed tile row stride for TMA (24 floats = 96B rows)
#define Y0S     12

__device__ __forceinline__ unsigned smem_u32(const void* p) {
    return (unsigned)__cvta_generic_to_shared(p);
}
__device__ __forceinline__ void cp16(unsigned dst, const void* src) {
    asm volatile("cp.async.cg.shared.global [%0], [%1], 16;\n" :: "r"(dst), "l"(src) : "memory");
}
__device__ __forceinline__ void cp_commit() {
    asm volatile("cp.async.commit_group;\n" ::: "memory");
}
template<int N> __device__ __forceinline__ void cp_wait() {
    asm volatile("cp.async.wait_group %0;\n" :: "n"(N) : "memory");
}
__device__ __forceinline__ void tma_store2d(const void* map, int x, int y, unsigned smem) {
    asm volatile("cp.async.bulk.tensor.2d.global.shared::cta.tile.bulk_group [%0, {%1, %2}], [%3];"
                 :: "l"(map), "r"(x), "r"(y), "r"(smem) : "memory");
}
__device__ __forceinline__ void bulk_commit() {
    asm volatile("cp.async.bulk.commit_group;" ::: "memory");
}
template<int N> __device__ __forceinline__ void bulk_wait() {
    asm volatile("cp.async.bulk.wait_group %0;" :: "n"(N) : "memory");
}
__device__ __forceinline__ void fence_async_shared() {
    asm volatile("fence.proxy.async.shared::cta;" ::: "memory");
}

// 12-step sub-batch; P0 compile-time => seasonal state fully register-resident.
// Slots (P0+k)%24 for k=0..11 are distinct and untouched earlier this period,
// so each read sees the value from exactly 24 steps ago (matches reference).
template<int P0>
__device__ __forceinline__ void half12(
    const float* __restrict__ ysm, float* __restrict__ lb, float* __restrict__ sb,
    float* __restrict__ dt,
    float a, float oma, float& lev, float& llev, float (&sbuf)[SEASK])
{
    float yt[12], q_[12], nl_[12];
    #pragma unroll
    for (int m = 0; m < 3; m++) {
        const float4 v = *(const float4*)(ysm + 4 * m);
        yt[4*m+0] = v.x; yt[4*m+1] = v.y; yt[4*m+2] = v.z; yt[4*m+3] = v.w;
    }
    #pragma unroll
    for (int k = 0; k < 12; k++) {
        const int pp = (P0 + k) % SEASK;
        const float sv = sbuf[pp];
        q_[k]    = a * __fdividef(yt[k], sv);
        sbuf[pp] = oma * sv;                       // fold (1-a)*seas in place
    }
    #pragma unroll
    for (int k = 0; k < 12; k++) { nl_[k] = fmaf(oma, lev, q_[k]); lev = nl_[k]; }
    #pragma unroll
    for (int k = 0; k < 12; k++) {
        const int pp = (P0 + k) % SEASK;
        sbuf[pp] = fmaf(a, __fdividef(yt[k], nl_[k]), sbuf[pp]);
    }
    // stage packed tiles (for TMA) + logs
    #pragma unroll
    for (int m = 0; m < 3; m++) {
        *(float4*)(lb + 4*m) = make_float4(nl_[4*m], nl_[4*m+1], nl_[4*m+2], nl_[4*m+3]);
        *(float4*)(sb + 4*m) = make_float4(sbuf[(P0+4*m)   % SEASK], sbuf[(P0+4*m+1) % SEASK],
                                           sbuf[(P0+4*m+2) % SEASK], sbuf[(P0+4*m+3) % SEASK]);
        float d0, d1, d2, d3, ll;
        ll = __logf(nl_[4*m+0]); d0 = ll - llev; llev = ll;
        ll = __logf(nl_[4*m+1]); d1 = ll - llev; llev = ll;
        ll = __logf(nl_[4*m+2]); d2 = ll - llev; llev = ll;
        ll = __logf(nl_[4*m+3]); d3 = ll - llev; llev = ll;
        *(float4*)(dt + 4*m) = make_float4(d0, d1, d2, d3);
    }
}

__global__ __launch_bounds__(BLOCK) void es_fwd_kernel(
    const __grid_constant__ CUtensorMap tml,   // levels [512 x 32768]
    const __grid_constant__ CUtensorMap tms,   // seas   [536 x 32768]
    const float* __restrict__ y,
    const int*   __restrict__ idxs,
    const float* __restrict__ lev_sms_p,
    const float* __restrict__ init_seas_p,
    float* __restrict__ out)
{
    __shared__ __align__(16) float ybuf[3][BLOCK * RSTRIDE];
    __shared__ __align__(16) float y0buf[BLOCK * Y0S];
    __shared__ __align__(16) float ltile[2][BLOCK * LPACK];   // packed for TMA
    __shared__ __align__(16) float stile[2][BLOCK * LPACK];   // packed for TMA
    __shared__ __align__(16) float dtile[BLOCK * RSTRIDE];

    const int tid = threadIdx.x;
    const int s0  = blockIdx.x * BLOCK;
    const int s   = s0 + tid;

    float* gs = out + (size_t)NS * LEVW;
    float* gd = gs  + (size_t)NS * SEAW;
    float* gl = out;

    const int idx = idxs[s];
    // reference derives BOTH smoothing params from lev_sms (its own quirk)
    const float a   = 1.0f / (1.0f + __expf(-lev_sms_p[idx]));
    const float oma = 1.0f - a;

    // ---- async y loads first ----
    const char* ybase = (const char*)(y + (size_t)s0 * NT);
    const unsigned ysb[3] = { smem_u32(ybuf[0]), smem_u32(ybuf[1]), smem_u32(ybuf[2]) };
    #pragma unroll
    for (int j = 0; j < 2; j++) {
        const int f = tid + 32 * j;
        const int row = f >> 1, col = f & 1;
        cp16(smem_u32(y0buf) + row * (Y0S * 4) + col * 16,
             ybase + row * (NT * 4) + col * 16);
    }
    cp_commit();
    #pragma unroll
    for (int p = 0; p < 2; p++) {
        #pragma unroll
        for (int j = 0; j < 6; j++) {
            const int f = tid + 32 * j;
            const int row = f / 6, col = f % 6;
            cp16(ysb[p] + row * (RSTRIDE * 4) + col * 16,
                 ybase + 32 + 96 * p + row * (NT * 4) + col * 16);
        }
        cp_commit();
    }

    // ---- seasonal state in registers; emit seas cols 0..23 ----
    float sbuf[SEASK];
    {
        const float4* isr = (const float4*)(init_seas_p + (size_t)idx * SEASK);
        float4* gsr = (float4*)(gs + (size_t)s * SEAW);
        #pragma unroll
        for (int qd = 0; qd < 6; qd++) {
            float4 v = isr[qd];
            v.x = __expf(v.x); v.y = __expf(v.y); v.z = __expf(v.z); v.w = __expf(v.w);
            sbuf[4*qd+0] = v.x; sbuf[4*qd+1] = v.y;
            sbuf[4*qd+2] = v.z; sbuf[4*qd+3] = v.w;
            __stcs(gsr + qd, v);
        }
    }

    float lev, llev;

    // ================= peel: steps 0..7 =================
    cp_wait<2>();
    __syncwarp();
    {
        const float4 v0 = *(const float4*)(y0buf + tid * Y0S);
        const float4 v1 = *(const float4*)(y0buf + tid * Y0S + 4);
        float yt[8] = {v0.x, v0.y, v0.z, v0.w, v1.x, v1.y, v1.z, v1.w};
        float q_[8], nl_[8], dt_[8];

        const float st0 = sbuf[0];
        lev  = __fdividef(yt[0], st0);
        llev = __logf(lev);
        nl_[0] = lev; dt_[0] = 0.0f;

        #pragma unroll
        for (int k = 1; k < 8; k++) {
            const float sv = sbuf[k];
            q_[k]   = a * __fdividef(yt[k], sv);
            sbuf[k] = oma * sv;
        }
        #pragma unroll
        for (int k = 1; k < 8; k++) { nl_[k] = fmaf(oma, lev, q_[k]); lev = nl_[k]; }
        #pragma unroll
        for (int k = 1; k < 8; k++)
            sbuf[k] = fmaf(a, __fdividef(yt[k], nl_[k]), sbuf[k]);
        #pragma unroll
        for (int k = 1; k < 8; k++) {
            const float ll = __logf(nl_[k]);
            dt_[k] = ll - llev; llev = ll;
        }

        float* lb = ltile[0] + tid * LPACK;
        float* sb = stile[0] + tid * LPACK;
        float* dt = dtile    + tid * RSTRIDE;
        *(float4*)(lb)     = make_float4(nl_[0], nl_[1], nl_[2], nl_[3]);
        *(float4*)(lb + 4) = make_float4(nl_[4], nl_[5], nl_[6], nl_[7]);
        *(float4*)(sb)     = make_float4(st0, sbuf[1], sbuf[2], sbuf[3]);  // col 24 = init_seas[:,0]
        *(float4*)(sb + 4) = make_float4(sbuf[4], sbuf[5], sbuf[6], sbuf[7]);
        *(float4*)(dt)     = make_float4(dt_[0], dt_[1], dt_[2], dt_[3]);
        *(float4*)(dt + 4) = make_float4(dt_[4], dt_[5], dt_[6], dt_[7]);
        __syncwarp();

        #pragma unroll
        for (int j = 0; j < 2; j++) {
            const int f = tid + 32 * j;
            const int row = f >> 1, qd = f & 1;
            __stcs((float4*)(gl + (size_t)(s0 + row) * LEVW) + qd,
                   ((const float4*)(ltile[0] + row * LPACK))[qd]);
            __stcs((float4*)(gs + (size_t)(s0 + row) * SEAW + SEASK) + qd,
                   ((const float4*)(stile[0] + row * LPACK))[qd]);
        }
        #pragma unroll
        for (int j = 0; j < 7; j++) {
            const int i = tid + 32 * j;
            const int row = i / 7, k = i % 7;
            __stcs(gd + (size_t)(s0 + row) * LOGW + k, dtile[row * RSTRIDE + 1 + k]);
        }
        __syncwarp();
    }

    // ================= 21 steady periods of 24 steps =================
    #pragma unroll 1
    for (int p = 0; p < NPER; p++) {
        // input pipeline: prefetch period p+2, wait for period p
        if (p + 2 < NPER) {
            const char* yb = ybase + 32 + (size_t)(p + 2) * 96;
            const unsigned d = ysb[(p + 2) % 3];
            #pragma unroll
            for (int j = 0; j < 6; j++) {
                const int f = tid + 32 * j;
                const int row = f / 6, col = f % 6;
                cp16(d + row * (RSTRIDE * 4) + col * 16, yb + row * (NT * 4) + col * 16);
            }
            cp_commit();
            cp_wait<2>();
        } else {
            cp_wait<0>();
        }
        // TMA from period p-2 must be done before overwriting tile buffer p&1
        if (tid == 0) bulk_wait<1>();
        __syncwarp();

        const float* ysm = ybuf[p % 3] + tid * RSTRIDE;
        float* lb = ltile[p & 1] + tid * LPACK;
        float* sb = stile[p & 1] + tid * LPACK;
        float* dt = dtile + tid * RSTRIDE;

        half12< 8>(ysm,      lb,      sb,      dt,      a, oma, lev, llev, sbuf);
        half12<20>(ysm + 12, lb + 12, sb + 12, dt + 12, a, oma, lev, llev, sbuf);

        fence_async_shared();
        __syncwarp();

        const int tp = 8 + 24 * p;
        if (tid == 0) {
            tma_store2d(&tml, tp,         s0, smem_u32(ltile[p & 1]));
            tma_store2d(&tms, tp + SEASK, s0, smem_u32(stile[p & 1]));
            bulk_commit();
        }

        // log_diff: odd row stride (2044B) forbids vector stores; scalar coalesced
        #pragma unroll
        for (int j = 0; j < 24; j++) {
            const int i = tid + 32 * j;
            const int row = i / 24, k = i % 24;
            __stcs(gd + (size_t)(s0 + row) * LOGW + tp - 1 + k, dtile[row * RSTRIDE + k]);
        }
        __syncwarp();
    }
    if (tid == 0) bulk_wait<0>();
}

extern "C" void kernel_launch(void* const* d_in, const int* in_sizes, int n_in,
                              void* d_out, int out_size)
{
    const float* y         = (const float*)d_in[0];
    const int*   idxs      = (const int*)  d_in[1];
    const float* lev_sms   = (const float*)d_in[2];
    const float* init_seas = (const float*)d_in[4];  // d_in[3] unused (reference quirk)
    float* out = (float*)d_out;

    // Build TMA descriptors for the two vectorizable output streams.
    typedef CUresult (*EncodeFn)(CUtensorMap*, CUtensorMapDataType, cuuint32_t, void*,
                                 const cuuint64_t*, const cuuint64_t*, const cuuint32_t*,
                                 const cuuint32_t*, CUtensorMapInterleave, CUtensorMapSwizzle,
                                 CUtensorMapL2promotion, CUtensorMapFloatOOBfill);
    EncodeFn enc = nullptr;
    cudaDriverEntryPointQueryResult qr;
    cudaGetDriverEntryPointByVersion("cuTensorMapEncodeTiled", (void**)&enc, 12000,
                                     cudaEnableDefault, &qr);

    CUtensorMap tml, tms;
    {
        float* gl = out;
        cuuint64_t dims[2]    = { (cuuint64_t)LEVW, (cuuint64_t)NS };
        cuuint64_t strides[1] = { (cuuint64_t)LEVW * 4 };
        cuuint32_t box[2]     = { 24, 32 };
        cuuint32_t es[2]      = { 1, 1 };
        enc(&tml, CU_TENSOR_MAP_DATA_TYPE_FLOAT32, 2, gl, dims, strides, box, es,
            CU_TENSOR_MAP_INTERLEAVE_NONE, CU_TENSOR_MAP_SWIZZLE_NONE,
            CU_TENSOR_MAP_L2_PROMOTION_L2_128B, CU_TENSOR_MAP_FLOAT_OOB_FILL_NONE);
    }
    {
        float* gsp = out + (size_t)NS * LEVW;
        cuuint64_t dims[2]    = { (cuuint64_t)SEAW, (cuuint64_t)NS };
        cuuint64_t strides[1] = { (cuuint64_t)SEAW * 4 };
        cuuint32_t box[2]     = { 24, 32 };
        cuuint32_t es[2]      = { 1, 1 };
        enc(&tms, CU_TENSOR_MAP_DATA_TYPE_FLOAT32, 2, gsp, dims, strides, box, es,
            CU_TENSOR_MAP_INTERLEAVE_NONE, CU_TENSOR_MAP_SWIZZLE_NONE,
            CU_TENSOR_MAP_L2_PROMOTION_L2_128B, CU_TENSOR_MAP_FLOAT_OOB_FILL_NONE);
    }

    es_fwd_kernel<<<NS / BLOCK, BLOCK>>>(tml, tms, y, idxs, lev_sms, init_seas, out);
}

// round 8
// speedup vs baseline: 1.0545x; 1.0233x over previous
#include <cuda_runtime.h>
#include <cuda.h>

#define NS      32768
#define NT      512
#define SEASK   24
#define LEVW    512
#define SEAW    536
#define LOGW    511

#define NWARP   32          // series per block (= compute lanes)
#define BLOCK   64          // warp 0: compute, warp 1: IO
#define NPER    21
#define RSTRIDE 28          // y smem row stride: conflict-free .128
#define LPACK   24          // packed tile rows for TMA
#define Y0S     12

__device__ __forceinline__ unsigned smem_u32(const void* p) {
    return (unsigned)__cvta_generic_to_shared(p);
}
__device__ __forceinline__ void cp16(unsigned dst, const void* src) {
    asm volatile("cp.async.cg.shared.global [%0], [%1], 16;\n" :: "r"(dst), "l"(src) : "memory");
}
__device__ __forceinline__ void cp_commit() {
    asm volatile("cp.async.commit_group;\n" ::: "memory");
}
template<int N> __device__ __forceinline__ void cp_wait() {
    asm volatile("cp.async.wait_group %0;\n" :: "n"(N) : "memory");
}
__device__ __forceinline__ void tma_store2d(const void* map, int x, int y, unsigned smem) {
    asm volatile("cp.async.bulk.tensor.2d.global.shared::cta.tile.bulk_group [%0, {%1, %2}], [%3];"
                 :: "l"(map), "r"(x), "r"(y), "r"(smem) : "memory");
}
__device__ __forceinline__ void bulk_commit() {
    asm volatile("cp.async.bulk.commit_group;" ::: "memory");
}
template<int N> __device__ __forceinline__ void bulk_wait() {
    asm volatile("cp.async.bulk.wait_group %0;" :: "n"(N) : "memory");
}
__device__ __forceinline__ void fence_async_shared() {
    asm volatile("fence.proxy.async.shared::cta;" ::: "memory");
}

// 12-step sub-batch, P0 compile-time. Slots (P0+k)%24 distinct within the
// period -> each read sees the value from exactly 24 steps ago (matches ref).
// yt is reloaded from smem for the second divide batch to cut live registers.
template<int P0>
__device__ __forceinline__ void half12(
    const float* __restrict__ ysm, float* __restrict__ lb, float* __restrict__ sb,
    float* __restrict__ db,
    float a, float oma, float& lev, float& llev, float (&sbuf)[SEASK])
{
    float q_[12], nl_[12];
    #pragma unroll
    for (int k = 0; k < 12; k++) {
        const int pp = (P0 + k) % SEASK;
        const float sv = sbuf[pp];
        q_[k]    = a * __fdividef(ysm[k], sv);
        sbuf[pp] = oma * sv;                        // fold (1-a)*seas in place
    }
    #pragma unroll
    for (int k = 0; k < 12; k++) { nl_[k] = fmaf(oma, lev, q_[k]); lev = nl_[k]; }
    #pragma unroll
    for (int k = 0; k < 12; k++) {
        const int pp = (P0 + k) % SEASK;
        sbuf[pp] = fmaf(a, __fdividef(ysm[k], nl_[k]), sbuf[pp]);
    }
    #pragma unroll
    for (int m = 0; m < 3; m++) {
        *(float4*)(lb + 4*m) = make_float4(nl_[4*m], nl_[4*m+1], nl_[4*m+2], nl_[4*m+3]);
        *(float4*)(sb + 4*m) = make_float4(sbuf[(P0+4*m)   % SEASK], sbuf[(P0+4*m+1) % SEASK],
                                           sbuf[(P0+4*m+2) % SEASK], sbuf[(P0+4*m+3) % SEASK]);
        float d0, d1, d2, d3, ll;
        ll = __logf(nl_[4*m+0]); d0 = ll - llev; llev = ll;
        ll = __logf(nl_[4*m+1]); d1 = ll - llev; llev = ll;
        ll = __logf(nl_[4*m+2]); d2 = ll - llev; llev = ll;
        ll = __logf(nl_[4*m+3]); d3 = ll - llev; llev = ll;
        *(float4*)(db + 4*m) = make_float4(d0, d1, d2, d3);
    }
}

__global__ __launch_bounds__(BLOCK, 7) void es_fwd_kernel(
    const __grid_constant__ CUtensorMap tml,
    const __grid_constant__ CUtensorMap tms,
    const float* __restrict__ y,
    const int*   __restrict__ idxs,
    const float* __restrict__ lev_sms_p,
    const float* __restrict__ init_seas_p,
    float* __restrict__ out)
{
    __shared__ __align__(16) float ybuf[3][NWARP * RSTRIDE];
    __shared__ __align__(16) float y0buf[NWARP * Y0S];
    __shared__ __align__(16) float ltile[2][NWARP * LPACK];
    __shared__ __align__(16) float stile[2][NWARP * LPACK];
    __shared__ __align__(16) float dtile[2][NWARP * LPACK];

    const int tid  = threadIdx.x;
    const int wid  = tid >> 5;
    const int lane = tid & 31;
    const int s0   = blockIdx.x * NWARP;

    float* gl = out;
    float* gs = out + (size_t)NS * LEVW;
    float* gd = gs  + (size_t)NS * SEAW;

    if (wid == 0) {
        // ===================== COMPUTE WARP =====================
        const int s   = s0 + lane;
        const int idx = idxs[s];
        // reference derives BOTH smoothing params from lev_sms (its own quirk)
        const float a   = 1.0f / (1.0f + __expf(-lev_sms_p[idx]));
        const float oma = 1.0f - a;

        const char* ybase = (const char*)(y + (size_t)s0 * NT);
        const unsigned ysb[3] = { smem_u32(ybuf[0]), smem_u32(ybuf[1]), smem_u32(ybuf[2]) };

        // async y loads: G0 = steps 0..7, G1/G2 = periods 0,1
        #pragma unroll
        for (int j = 0; j < 2; j++) {
            const int f = lane + 32 * j;
            const int row = f >> 1, col = f & 1;
            cp16(smem_u32(y0buf) + row * (Y0S * 4) + col * 16,
                 ybase + row * (NT * 4) + col * 16);
        }
        cp_commit();
        #pragma unroll
        for (int p = 0; p < 2; p++) {
            #pragma unroll
            for (int j = 0; j < 6; j++) {
                const int f = lane + 32 * j;
                const int row = f / 6, col = f % 6;
                cp16(ysb[p] + row * (RSTRIDE * 4) + col * 16,
                     ybase + 32 + 96 * p + row * (NT * 4) + col * 16);
            }
            cp_commit();
        }

        // seasonal state in registers; emit seas cols 0..23
        float sbuf[SEASK];
        {
            const float4* isr = (const float4*)(init_seas_p + (size_t)idx * SEASK);
            float4* gsr = (float4*)(gs + (size_t)s * SEAW);
            #pragma unroll
            for (int qd = 0; qd < 6; qd++) {
                float4 v = isr[qd];
                v.x = __expf(v.x); v.y = __expf(v.y); v.z = __expf(v.z); v.w = __expf(v.w);
                sbuf[4*qd+0] = v.x; sbuf[4*qd+1] = v.y;
                sbuf[4*qd+2] = v.z; sbuf[4*qd+3] = v.w;
                __stcs(gsr + qd, v);
            }
        }

        float lev, llev;

        // ---- peel steps 0..7 (direct stores; tiny) ----
        cp_wait<2>();
        __syncwarp();
        {
            const float4 v0 = *(const float4*)(y0buf + lane * Y0S);
            const float4 v1 = *(const float4*)(y0buf + lane * Y0S + 4);
            float yt[8] = {v0.x, v0.y, v0.z, v0.w, v1.x, v1.y, v1.z, v1.w};
            float q_[8], nl_[8], dt_[8];

            const float st0 = sbuf[0];
            lev  = __fdividef(yt[0], st0);
            llev = __logf(lev);
            nl_[0] = lev; dt_[0] = 0.0f;

            #pragma unroll
            for (int k = 1; k < 8; k++) {
                const float sv = sbuf[k];
                q_[k]   = a * __fdividef(yt[k], sv);
                sbuf[k] = oma * sv;
            }
            #pragma unroll
            for (int k = 1; k < 8; k++) { nl_[k] = fmaf(oma, lev, q_[k]); lev = nl_[k]; }
            #pragma unroll
            for (int k = 1; k < 8; k++)
                sbuf[k] = fmaf(a, __fdividef(yt[k], nl_[k]), sbuf[k]);
            #pragma unroll
            for (int k = 1; k < 8; k++) {
                const float ll = __logf(nl_[k]);
                dt_[k] = ll - llev; llev = ll;
            }

            float* lb = ltile[0] + lane * 8;     // temp staging (8-wide packed)
            float* sb = stile[0] + lane * 8;
            float* db = dtile[0] + lane * 8;
            *(float4*)(lb)     = make_float4(nl_[0], nl_[1], nl_[2], nl_[3]);
            *(float4*)(lb + 4) = make_float4(nl_[4], nl_[5], nl_[6], nl_[7]);
            *(float4*)(sb)     = make_float4(st0, sbuf[1], sbuf[2], sbuf[3]);
            *(float4*)(sb + 4) = make_float4(sbuf[4], sbuf[5], sbuf[6], sbuf[7]);
            *(float4*)(db)     = make_float4(dt_[0], dt_[1], dt_[2], dt_[3]);
            *(float4*)(db + 4) = make_float4(dt_[4], dt_[5], dt_[6], dt_[7]);
            __syncwarp();

            #pragma unroll
            for (int j = 0; j < 2; j++) {
                const int f = lane + 32 * j;
                const int row = f >> 1, qd = f & 1;
                __stcs((float4*)(gl + (size_t)(s0 + row) * LEVW) + qd,
                       ((const float4*)(ltile[0] + row * 8))[qd]);
                __stcs((float4*)(gs + (size_t)(s0 + row) * SEAW + SEASK) + qd,
                       ((const float4*)(stile[0] + row * 8))[qd]);
            }
            #pragma unroll
            for (int j = 0; j < 7; j++) {
                const int i = lane + 32 * j;
                const int row = i / 7, k = i % 7;
                __stcs(gd + (size_t)(s0 + row) * LOGW + k, dtile[0][row * 8 + 1 + k]);
            }
            __syncwarp();
        }

        // ---- 21 steady periods ----
        #pragma unroll 1
        for (int p = 0; p < NPER; p++) {
            if (p + 2 < NPER) {
                const char* yb = ybase + 32 + (size_t)(p + 2) * 96;
                const unsigned d = ysb[(p + 2) % 3];
                #pragma unroll
                for (int j = 0; j < 6; j++) {
                    const int f = lane + 32 * j;
                    const int row = f / 6, col = f % 6;
                    cp16(d + row * (RSTRIDE * 4) + col * 16, yb + row * (NT * 4) + col * 16);
                }
                cp_commit();
                cp_wait<2>();
            } else {
                cp_wait<0>();
            }
            __syncwarp();

            const float* ysm = ybuf[p % 3] + lane * RSTRIDE;
            float* lb = ltile[p & 1] + lane * LPACK;
            float* sb = stile[p & 1] + lane * LPACK;
            float* db = dtile[p & 1] + lane * LPACK;

            half12< 8>(ysm,      lb,      sb,      db,      a, oma, lev, llev, sbuf);
            half12<20>(ysm + 12, lb + 12, sb + 12, db + 12, a, oma, lev, llev, sbuf);

            __syncthreads();   // B_p: tiles[p&1] ready; IO drained & TMA-completed prior use
        }
    } else {
        // ===================== IO WARP =====================
        #pragma unroll 1
        for (int p = 0; p < NPER; p++) {
            __syncthreads();   // wait B_p
            const int b  = p & 1;
            const int tp = 8 + 24 * p;

            if (lane == 0) {
                fence_async_shared();
                tma_store2d(&tml, tp,         s0, smem_u32(ltile[b]));
                tma_store2d(&tms, tp + SEASK, s0, smem_u32(stile[b]));
                bulk_commit();
            }

            // log_diff: flat smem (i = 24*row + k), coalesced scalar streaming stores
            const float* df = dtile[b];
            #pragma unroll
            for (int j = 0; j < 24; j++) {
                const int i = lane + 32 * j;
                const int row = i / 24, k = i % 24;
                __stcs(gd + (size_t)(s0 + row) * LOGW + tp - 1 + k, df[i]);
            }

            if (lane == 0) bulk_wait<0>();   // tiles fully consumed before reuse
        }
    }
}

extern "C" void kernel_launch(void* const* d_in, const int* in_sizes, int n_in,
                              void* d_out, int out_size)
{
    const float* y         = (const float*)d_in[0];
    const int*   idxs      = (const int*)  d_in[1];
    const float* lev_sms   = (const float*)d_in[2];
    const float* init_seas = (const float*)d_in[4];  // d_in[3] unused (reference quirk)
    float* out = (float*)d_out;

    typedef CUresult (*EncodeFn)(CUtensorMap*, CUtensorMapDataType, cuuint32_t, void*,
                                 const cuuint64_t*, const cuuint64_t*, const cuuint32_t*,
                                 const cuuint32_t*, CUtensorMapInterleave, CUtensorMapSwizzle,
                                 CUtensorMapL2promotion, CUtensorMapFloatOOBfill);
    EncodeFn enc = nullptr;
    cudaDriverEntryPointQueryResult qr;
    cudaGetDriverEntryPointByVersion("cuTensorMapEncodeTiled", (void**)&enc, 12000,
                                     cudaEnableDefault, &qr);

    CUtensorMap tml, tms;
    {
        cuuint64_t dims[2]    = { (cuuint64_t)LEVW, (cuuint64_t)NS };
        cuuint64_t strides[1] = { (cuuint64_t)LEVW * 4 };
        cuuint32_t box[2]     = { 24, 32 };
        cuuint32_t es[2]      = { 1, 1 };
        enc(&tml, CU_TENSOR_MAP_DATA_TYPE_FLOAT32, 2, out, dims, strides, box, es,
            CU_TENSOR_MAP_INTERLEAVE_NONE, CU_TENSOR_MAP_SWIZZLE_NONE,
            CU_TENSOR_MAP_L2_PROMOTION_L2_128B, CU_TENSOR_MAP_FLOAT_OOB_FILL_NONE);
    }
    {
        float* gsp = out + (size_t)NS * LEVW;
        cuuint64_t dims[2]    = { (cuuint64_t)SEAW, (cuuint64_t)NS };
        cuuint64_t strides[1] = { (cuuint64_t)SEAW * 4 };
        cuuint32_t box[2]     = { 24, 32 };
        cuuint32_t es[2]      = { 1, 1 };
        enc(&tms, CU_TENSOR_MAP_DATA_TYPE_FLOAT32, 2, gsp, dims, strides, box, es,
            CU_TENSOR_MAP_INTERLEAVE_NONE, CU_TENSOR_MAP_SWIZZLE_NONE,
            CU_TENSOR_MAP_L2_PROMOTION_L2_128B, CU_TENSOR_MAP_FLOAT_OOB_FILL_NONE);
    }

    es_fwd_kernel<<<NS / NWARP, BLOCK>>>(tml, tms, y, idxs, lev_sms, init_seas, out);
}